// round 14
// baseline (speedup 1.0000x reference)
#include <cuda_runtime.h>
#include <cstdint>

#define NN 100000
#define EE 1600000
#define DD 128
#define DEE 16
#define GG 512
#define BN_EPS 1e-5f

// ---------------- scratch (device globals; ONLY referenced from device code) ----------------
__device__ __align__(16) float g_xw[NN * DD];   // X@W (layer1 raw; layer2 pre-scaled by dinv)
__device__ __align__(16) float g_h[NN * DD];    // layer1 output (post BN+ReLU)
__device__ float g_dinv[NN];
__device__ int   g_degi[NN];
__device__ int   g_doff[NN + 1];
__device__ int   g_dcur[NN];
__device__ int   g_src32[EE];
__device__ int   g_dst32[EE];
__device__ int   g_ssorted[EE];
__device__ int   g_egr[EE];
__device__ int   g_eperm[EE];
__device__ int   g_nb32[NN];
__device__ int   g_ecnt[GG];
__device__ int   g_gcnt[GG];
__device__ int   g_eoff[GG + 1];
__device__ int   g_ecur[GG];
__device__ __align__(16) float g_gsum[GG * DD];
__device__ __align__(16) float g_esum[GG * DD];
__device__ int   g_is64;

__device__ __forceinline__ void red_add_v4(float* addr, float4 v) {
    asm volatile("red.global.add.v4.f32 [%0], {%1, %2, %3, %4};"
                 :: "l"(__cvta_generic_to_global(addr)),
                    "f"(v.x), "f"(v.y), "f"(v.z), "f"(v.w)
                 : "memory");
}
__device__ __forceinline__ void red_add_f32(float* addr, float v) {
    asm volatile("red.global.add.f32 [%0], %1;"
                 :: "l"(__cvta_generic_to_global(addr)), "f"(v) : "memory");
}
__device__ __forceinline__ int clampi(int v, int lo, int hi) {
    return min(max(v, lo), hi);
}

// ---------------- init + dtype probe (merged) ----------------
__global__ void k_init(const int* __restrict__ ei_raw) {
    if (blockIdx.x == 0) {
        __shared__ int nz;
        if (threadIdx.x == 0) nz = 0;
        __syncthreads();
        for (int i = threadIdx.x; i < 1024; i += blockDim.x)
            if (ei_raw[2 * i + 1] != 0) nz = 1;   // int64 iff all odd words zero
        __syncthreads();
        if (threadIdx.x == 0) g_is64 = (nz == 0) ? 1 : 0;
    }
    int i = blockIdx.x * blockDim.x + threadIdx.x;
    int stride = gridDim.x * blockDim.x;
    for (int idx = i; idx < NN; idx += stride) {
        g_degi[idx] = 0;
        if (idx < GG * DD) { g_gsum[idx] = 0.f; g_esum[idx] = 0.f; }
        if (idx < GG) { g_ecnt[idx] = 0; g_gcnt[idx] = 0; }
    }
}

// ---------------- edge prep ----------------
__global__ void k_edge_prep(const void* __restrict__ ei_raw,
                            const void* __restrict__ batch_raw) {
    __shared__ int hist[GG];
    for (int t = threadIdx.x; t < GG; t += blockDim.x) hist[t] = 0;
    __syncthreads();
    const int is64 = g_is64;
    const int*       ei32 = (const int*)ei_raw;
    const long long* ei64 = (const long long*)ei_raw;
    const int*       bt32 = (const int*)batch_raw;
    const long long* bt64 = (const long long*)batch_raw;
    int i0 = blockIdx.x * blockDim.x + threadIdx.x;
    int stride = gridDim.x * blockDim.x;
    for (int e = i0; e < EE; e += stride) {
        int s, d;
        if (is64) { s = (int)ei64[e]; d = (int)ei64[EE + e]; }
        else      { s = ei32[e];      d = ei32[EE + e]; }
        s = clampi(s, 0, NN - 1);
        d = clampi(d, 0, NN - 1);
        g_src32[e] = s;
        g_dst32[e] = d;
        atomicAdd(&g_degi[d], 1);
        int gr = is64 ? (int)bt64[s] : bt32[s];
        gr = clampi(gr, 0, GG - 1);
        g_egr[e] = gr;
        atomicAdd(&hist[gr], 1);
    }
    __syncthreads();
    for (int t = threadIdx.x; t < GG; t += blockDim.x)
        if (hist[t]) atomicAdd(&g_ecnt[t], hist[t]);
}

// ---------------- node prep ----------------
__global__ void k_node_prep(const void* __restrict__ batch_raw) {
    __shared__ int hist[GG];
    for (int t = threadIdx.x; t < GG; t += blockDim.x) hist[t] = 0;
    __syncthreads();
    const int is64 = g_is64;
    const int*       bt32 = (const int*)batch_raw;
    const long long* bt64 = (const long long*)batch_raw;
    int i0 = blockIdx.x * blockDim.x + threadIdx.x;
    int stride = gridDim.x * blockDim.x;
    for (int v = i0; v < NN; v += stride) {
        int gr = is64 ? (int)bt64[v] : bt32[v];
        gr = clampi(gr, 0, GG - 1);
        g_nb32[v] = gr;
        atomicAdd(&hist[gr], 1);
    }
    __syncthreads();
    for (int t = threadIdx.x; t < GG; t += blockDim.x)
        if (hist[t]) atomicAdd(&g_gcnt[t], hist[t]);
}

// ---------------- per-graph edge scan ----------------
__global__ void k_scan_graph() {
    __shared__ int s[GG];
    int t = threadIdx.x;
    int v = g_ecnt[t];
    s[t] = v;
    __syncthreads();
    for (int off = 1; off < GG; off <<= 1) {
        int add = (t >= off) ? s[t - off] : 0;
        __syncthreads();
        s[t] += add;
        __syncthreads();
    }
    int excl = s[t] - v;
    g_eoff[t] = excl;
    g_ecur[t] = excl;
    if (t == GG - 1) g_eoff[GG] = s[t];
}

// ---------------- CSR-by-dst scan + dinv ----------------
#define SCH 98
__global__ void k_scan_nodes() {
    __shared__ int part[1024];
    int t = threadIdx.x;
    int base = t * SCH;
    int sum = 0;
    for (int i = 0; i < SCH; i++) {
        int idx = base + i;
        if (idx < NN) sum += g_degi[idx];
    }
    part[t] = sum;
    __syncthreads();
    for (int off = 1; off < 1024; off <<= 1) {
        int add = (t >= off) ? part[t - off] : 0;
        __syncthreads();
        part[t] += add;
        __syncthreads();
    }
    int run = part[t] - sum;
    for (int i = 0; i < SCH; i++) {
        int idx = base + i;
        if (idx < NN) {
            g_doff[idx] = run;
            g_dcur[idx] = run;
            int dg = g_degi[idx];
            g_dinv[idx] = rsqrtf((float)(dg + 1));
            run += dg;
        }
    }
    if (t == 1023) g_doff[NN] = EE;
}

// ---------------- merged scatter: ONE pass does both orderings ----------------
__global__ void k_escatter() {
    int i0 = blockIdx.x * blockDim.x + threadIdx.x;
    int stride = gridDim.x * blockDim.x;
    for (int e = i0; e < EE; e += stride) {
        int gr = g_egr[e];
        int p = atomicAdd(&g_ecur[gr], 1);
        if (p < EE) g_eperm[p] = e;
        int d = g_dst32[e];
        int q = atomicAdd(&g_dcur[d], 1);
        if (q < EE) g_ssorted[q] = g_src32[e];
    }
}

// ---------------- FFMA GEMM (proven), device-symbol-safe I/O ----------------
// LAYER 1: g_xw = Xarg @ W (raw).  LAYER 2: g_xw = (g_h @ W) * dinv[row].
template <int LAYER>
__global__ void __launch_bounds__(256) k_gemm_scale(const float* __restrict__ Xarg,
                                                    const float* __restrict__ W) {
    const float* __restrict__ Xp = (LAYER == 2) ? (const float*)g_h : Xarg;
    float* __restrict__ Out = g_xw;
    __shared__ __align__(16) float Xs[64 * 16];
    __shared__ __align__(16) float Ws[16 * 128];
    int tid = threadIdx.x;
    int tx = tid & 31, ty = tid >> 5;
    int r0 = blockIdx.x * 64;
    float acc[8][4];
#pragma unroll
    for (int i = 0; i < 8; i++)
#pragma unroll
        for (int j = 0; j < 4; j++) acc[i][j] = 0.f;

    for (int k0 = 0; k0 < 128; k0 += 16) {
        {
            int i0 = tid * 4;
            int row = i0 >> 4, kk = i0 & 15;
            int gr = r0 + row;
            float4 v = make_float4(0.f, 0.f, 0.f, 0.f);
            if (gr < NN) v = *(const float4*)&Xp[gr * 128 + k0 + kk];
            *(float4*)&Xs[row * 16 + kk] = v;
        }
        {
            int i0 = tid * 8;
            int r = i0 >> 7, c = i0 & 127;
            *(float4*)&Ws[r * 128 + c]     = *(const float4*)&W[(k0 + r) * 128 + c];
            *(float4*)&Ws[r * 128 + c + 4] = *(const float4*)&W[(k0 + r) * 128 + c + 4];
        }
        __syncthreads();
#pragma unroll
        for (int kk = 0; kk < 16; kk++) {
            float4 b = *(float4*)&Ws[kk * 128 + 4 * tx];
#pragma unroll
            for (int i = 0; i < 8; i++) {
                float a = Xs[(8 * ty + i) * 16 + kk];
                acc[i][0] = fmaf(a, b.x, acc[i][0]);
                acc[i][1] = fmaf(a, b.y, acc[i][1]);
                acc[i][2] = fmaf(a, b.z, acc[i][2]);
                acc[i][3] = fmaf(a, b.w, acc[i][3]);
            }
        }
        __syncthreads();
    }
#pragma unroll
    for (int i = 0; i < 8; i++) {
        int row = r0 + 8 * ty + i;
        if (row < NN) {
            float s = (LAYER == 2) ? g_dinv[row] : 1.0f;
            float4 o = make_float4(acc[i][0] * s, acc[i][1] * s, acc[i][2] * s, acc[i][3] * s);
            *(float4*)&Out[row * 128 + 4 * tx] = o;
        }
    }
}

// ---------------- fused aggregation + BN + ReLU (+ pooled write for layer 2) ----------------
// Grid is EXACTLY 12500 blocks x 8 warps = 100000 warps (one per node); no partial blocks.
template <int LAYER>
__global__ void __launch_bounds__(256) k_agg_fused(const float* __restrict__ b,
                                                   const float* __restrict__ gam,
                                                   const float* __restrict__ bet,
                                                   const float* __restrict__ mu,
                                                   const float* __restrict__ var) {
    int warp = (blockIdx.x * blockDim.x + threadIdx.x) >> 5;
    int lane = threadIdx.x & 31;
    int v = warp;          // v < NN always (grid sized exactly)
    int dd = lane * 4;
    int lo = g_doff[v], hi = g_doff[v + 1];
    float dinv_v = g_dinv[v];

    float4 a0 = *(const float4*)&g_xw[v * 128 + dd];
    if (LAYER == 1) { a0.x *= dinv_v; a0.y *= dinv_v; a0.z *= dinv_v; a0.w *= dinv_v; }
    float4 a1 = make_float4(0.f, 0.f, 0.f, 0.f);
    float4 a2 = make_float4(0.f, 0.f, 0.f, 0.f);
    float4 a3 = make_float4(0.f, 0.f, 0.f, 0.f);
    int e = lo;
    for (; e + 3 < hi; e += 4) {
        int s0 = __ldg(&g_ssorted[e]);
        int s1 = __ldg(&g_ssorted[e + 1]);
        int s2 = __ldg(&g_ssorted[e + 2]);
        int s3 = __ldg(&g_ssorted[e + 3]);
        float4 v0 = *(const float4*)&g_xw[s0 * 128 + dd];
        float4 v1 = *(const float4*)&g_xw[s1 * 128 + dd];
        float4 v2 = *(const float4*)&g_xw[s2 * 128 + dd];
        float4 v3 = *(const float4*)&g_xw[s3 * 128 + dd];
        if (LAYER == 1) {
            float d0 = __ldg(&g_dinv[s0]);
            float d1 = __ldg(&g_dinv[s1]);
            float d2 = __ldg(&g_dinv[s2]);
            float d3 = __ldg(&g_dinv[s3]);
            a0.x = fmaf(v0.x, d0, a0.x); a0.y = fmaf(v0.y, d0, a0.y);
            a0.z = fmaf(v0.z, d0, a0.z); a0.w = fmaf(v0.w, d0, a0.w);
            a1.x = fmaf(v1.x, d1, a1.x); a1.y = fmaf(v1.y, d1, a1.y);
            a1.z = fmaf(v1.z, d1, a1.z); a1.w = fmaf(v1.w, d1, a1.w);
            a2.x = fmaf(v2.x, d2, a2.x); a2.y = fmaf(v2.y, d2, a2.y);
            a2.z = fmaf(v2.z, d2, a2.z); a2.w = fmaf(v2.w, d2, a2.w);
            a3.x = fmaf(v3.x, d3, a3.x); a3.y = fmaf(v3.y, d3, a3.y);
            a3.z = fmaf(v3.z, d3, a3.z); a3.w = fmaf(v3.w, d3, a3.w);
        } else {
            a0.x += v0.x; a0.y += v0.y; a0.z += v0.z; a0.w += v0.w;
            a1.x += v1.x; a1.y += v1.y; a1.z += v1.z; a1.w += v1.w;
            a2.x += v2.x; a2.y += v2.y; a2.z += v2.z; a2.w += v2.w;
            a3.x += v3.x; a3.y += v3.y; a3.z += v3.z; a3.w += v3.w;
        }
    }
    for (; e < hi; e++) {
        int s0 = __ldg(&g_ssorted[e]);
        float4 v0 = *(const float4*)&g_xw[s0 * 128 + dd];
        float d0 = (LAYER == 1) ? __ldg(&g_dinv[s0]) : 1.f;
        a0.x = fmaf(v0.x, d0, a0.x); a0.y = fmaf(v0.y, d0, a0.y);
        a0.z = fmaf(v0.z, d0, a0.z); a0.w = fmaf(v0.w, d0, a0.w);
    }
    float4 acc = make_float4(a0.x + a1.x + a2.x + a3.x,
                             a0.y + a1.y + a2.y + a3.y,
                             a0.z + a1.z + a2.z + a3.z,
                             a0.w + a1.w + a2.w + a3.w);

    float4 b4  = *(const float4*)&b[dd];
    float4 g4  = *(const float4*)&gam[dd];
    float4 t4  = *(const float4*)&bet[dd];
    float4 m4  = *(const float4*)&mu[dd];
    float4 v4  = *(const float4*)&var[dd];
    float s0c = g4.x * rsqrtf(v4.x + BN_EPS);
    float s1c = g4.y * rsqrtf(v4.y + BN_EPS);
    float s2c = g4.z * rsqrtf(v4.z + BN_EPS);
    float s3c = g4.w * rsqrtf(v4.w + BN_EPS);
    float c0 = (b4.x - m4.x) * s0c + t4.x;
    float c1 = (b4.y - m4.y) * s1c + t4.y;
    float c2 = (b4.z - m4.z) * s2c + t4.z;
    float c3 = (b4.w - m4.w) * s3c + t4.w;

    float4 r;
    r.x = fmaxf(dinv_v * acc.x * s0c + c0, 0.f);
    r.y = fmaxf(dinv_v * acc.y * s1c + c1, 0.f);
    r.z = fmaxf(dinv_v * acc.z * s2c + c2, 0.f);
    r.w = fmaxf(dinv_v * acc.w * s3c + c3, 0.f);

    if (LAYER == 1) {
        *(float4*)&g_h[v * 128 + dd] = r;
    } else {
        // nodes are sorted by graph; most 8-node blocks are single-graph -> pool in smem
        __shared__ float sred[8 * 128];
        int w = threadIdx.x >> 5;
        int bb = blockIdx.x * 8;
        int gr_first = __ldg(&g_nb32[bb]);
        int gr_last  = __ldg(&g_nb32[bb + 7]);
        if (gr_first == gr_last) {
            *(float4*)&sred[w * 128 + dd] = r;
            __syncthreads();
            int t = threadIdx.x;
            if (t < 128) {
                float tot = 0.f;
#pragma unroll
                for (int ww = 0; ww < 8; ww++) tot += sred[ww * 128 + t];
                red_add_f32(&g_gsum[gr_first * 128 + t], tot);
            }
        } else {
            __syncthreads();   // keep barrier count uniform (branch is block-uniform; safe either way)
            int gr = g_nb32[v];
            red_add_v4(&g_gsum[gr * 128 + dd], r);
        }
    }
}

// ---------------- edge encoder (FFMA, best-measured) ----------------
#define ECHUNKS 3
__global__ void __launch_bounds__(128) k_edge_enc(const float* __restrict__ EA,
                                                  const float* __restrict__ We1,
                                                  const float* __restrict__ be1) {
    int g = blockIdx.x;
    int lo = g_eoff[g], hi = g_eoff[g + 1];
    int cnt = hi - lo;
    int y = blockIdx.y;
    int cl = lo + (int)((long long)cnt * y / ECHUNKS);
    int ch = lo + (int)((long long)cnt * (y + 1) / ECHUNKS);
    int lane = threadIdx.x & 31;
    int w = threadIdx.x >> 5;

    float wr0[16], wr1[16], wr2[16], wr3[16];
#pragma unroll
    for (int k = 0; k < 16; k++) {
        wr0[k] = __ldg(&We1[k * 128 + lane]);
        wr1[k] = __ldg(&We1[k * 128 + 32 + lane]);
        wr2[k] = __ldg(&We1[k * 128 + 64 + lane]);
        wr3[k] = __ldg(&We1[k * 128 + 96 + lane]);
    }
    float br0 = __ldg(&be1[lane]);
    float br1 = __ldg(&be1[32 + lane]);
    float br2 = __ldg(&be1[64 + lane]);
    float br3 = __ldg(&be1[96 + lane]);
    float a0 = 0.f, a1 = 0.f, a2 = 0.f, a3 = 0.f;

    __shared__ __align__(16) float4 s_ea[128 * 4];
    for (int base = cl; base < ch; base += 128) {
        int n = min(128, ch - base);
        if ((int)threadIdx.x < n) {
            int e = g_eperm[base + threadIdx.x];
            const float4* p = (const float4*)&EA[(long long)e * 16];
            s_ea[threadIdx.x * 4 + 0] = __ldg(&p[0]);
            s_ea[threadIdx.x * 4 + 1] = __ldg(&p[1]);
            s_ea[threadIdx.x * 4 + 2] = __ldg(&p[2]);
            s_ea[threadIdx.x * 4 + 3] = __ldg(&p[3]);
        }
        __syncthreads();
        for (int j = w; j < n; j += 4) {
            float o0 = br0, o1 = br1, o2 = br2, o3 = br3;
#pragma unroll
            for (int q = 0; q < 4; q++) {
                float4 A = s_ea[j * 4 + q];
                float av[4] = {A.x, A.y, A.z, A.w};
#pragma unroll
                for (int kk = 0; kk < 4; kk++) {
                    int k = q * 4 + kk;
                    float aa = av[kk];
                    o0 = fmaf(aa, wr0[k], o0);
                    o1 = fmaf(aa, wr1[k], o1);
                    o2 = fmaf(aa, wr2[k], o2);
                    o3 = fmaf(aa, wr3[k], o3);
                }
            }
            a0 += fmaxf(o0, 0.f);
            a1 += fmaxf(o1, 0.f);
            a2 += fmaxf(o2, 0.f);
            a3 += fmaxf(o3, 0.f);
        }
        __syncthreads();
    }
    __shared__ float s_red[4][128];
    s_red[w][lane] = a0;
    s_red[w][32 + lane] = a1;
    s_red[w][64 + lane] = a2;
    s_red[w][96 + lane] = a3;
    __syncthreads();
    int t = threadIdx.x;
    float tot = s_red[0][t] + s_red[1][t] + s_red[2][t] + s_red[3][t];
    atomicAdd(&g_esum[g * 128 + t], tot);
}

// ---------------- final ----------------
__global__ void k_final(const float* __restrict__ We2, const float* __restrict__ be2,
                        float* __restrict__ out) {
    int g = blockIdx.x;
    int t = threadIdx.x;
    __shared__ float mh[128];
    int ec = g_ecnt[g];
    float inv = 1.0f / (float)max(ec, 1);
    mh[t] = g_esum[g * 128 + t] * inv;
    __syncthreads();
    float er = 0.f;
    if (ec > 0) {
#pragma unroll 8
        for (int k = 0; k < 128; k++)
            er = fmaf(mh[k], __ldg(&We2[k * 128 + t]), er);
        er += __ldg(&be2[t]);
    }
    float nc = (float)g_gcnt[g];
    float grp = g_gsum[g * 128 + t] / fmaxf(nc, 1.0f);
    out[g * 128 + t] = grp + er;
}

// ---------------- launch ----------------
extern "C" void kernel_launch(void* const* d_in, const int* in_sizes, int n_in,
                              void* d_out, int out_size) {
    const float* x     = (const float*)d_in[0];
    const void*  ei    = d_in[1];
    const void*  batch = d_in[2];
    const float* ea    = (const float*)d_in[3];
    int base = n_in - 16;
    const float* W1  = (const float*)d_in[base + 0];
    const float* b1  = (const float*)d_in[base + 1];
    const float* g1  = (const float*)d_in[base + 2];
    const float* bt1 = (const float*)d_in[base + 3];
    const float* m1  = (const float*)d_in[base + 4];
    const float* v1  = (const float*)d_in[base + 5];
    const float* W2  = (const float*)d_in[base + 6];
    const float* b2  = (const float*)d_in[base + 7];
    const float* g2  = (const float*)d_in[base + 8];
    const float* bt2 = (const float*)d_in[base + 9];
    const float* m2  = (const float*)d_in[base + 10];
    const float* v2  = (const float*)d_in[base + 11];
    const float* We1 = (const float*)d_in[base + 12];
    const float* be1 = (const float*)d_in[base + 13];
    const float* We2 = (const float*)d_in[base + 14];
    const float* be2 = (const float*)d_in[base + 15];
    float* out = (float*)d_out;

    static cudaStream_t sEnc = 0, sGemm = 0;
    static cudaEvent_t evRoot = 0, evScat = 0, evGemm1 = 0, evEnc = 0;
    if (sEnc == 0) {
        cudaStreamCreateWithFlags(&sEnc, cudaStreamNonBlocking);
        cudaStreamCreateWithFlags(&sGemm, cudaStreamNonBlocking);
        cudaEventCreateWithFlags(&evRoot,  cudaEventDisableTiming);
        cudaEventCreateWithFlags(&evScat,  cudaEventDisableTiming);
        cudaEventCreateWithFlags(&evGemm1, cudaEventDisableTiming);
        cudaEventCreateWithFlags(&evEnc,   cudaEventDisableTiming);
    }

    const int GEMM_BLOCKS = (NN + 63) / 64;

    // origin stream first op, then fork side streams
    k_init<<<512, 256>>>((const int*)ei);
    cudaEventRecord(evRoot, 0);

    // gemm1 (raw X@W1, input-only dep) on its own stream
    cudaStreamWaitEvent(sGemm, evRoot, 0);
    k_gemm_scale<1><<<GEMM_BLOCKS, 256, 0, sGemm>>>(x, W1);
    cudaEventRecord(evGemm1, sGemm);

    // node_prep (needs only batch + is64) on encoder stream
    cudaStreamWaitEvent(sEnc, evRoot, 0);
    k_node_prep<<<512, 256, 0, sEnc>>>(batch);

    // main chain: edge_prep -> scans -> merged scatter
    k_edge_prep<<<2048, 256>>>(ei, batch);
    k_scan_graph<<<1, GG>>>();
    k_scan_nodes<<<1, 1024>>>();
    k_escatter<<<2048, 256>>>();
    cudaEventRecord(evScat, 0);

    // encoder rides sEnc after the merged scatter
    cudaStreamWaitEvent(sEnc, evScat, 0);
    {
        dim3 grid(GG, ECHUNKS);
        k_edge_enc<<<grid, 128, 0, sEnc>>>(ea, We1, be1);
    }
    cudaEventRecord(evEnc, sEnc);

    const int AGG_BLOCKS = NN / 8;   // 12500 exact: one warp per node, no partial blocks
    cudaStreamWaitEvent(0, evGemm1, 0);
    k_agg_fused<1><<<AGG_BLOCKS, 256>>>(b1, g1, bt1, m1, v1);

    k_gemm_scale<2><<<GEMM_BLOCKS, 256>>>(nullptr, W2);
    cudaStreamWaitEvent(0, evEnc, 0);  // covers node_prep (g_nb32/g_gcnt) + encoder (g_esum)
    k_agg_fused<2><<<AGG_BLOCKS, 256>>>(b2, g2, bt2, m2, v2);

    k_final<<<GG, 128>>>(We2, be2, out);
}

// round 16
// speedup vs baseline: 1.2414x; 1.2414x over previous
#include <cuda_runtime.h>
#include <cstdint>

#define NN 100000
#define EE 1600000
#define DD 128
#define DEE 16
#define GG 512
#define BN_EPS 1e-5f

// ---------------- scratch (device globals; ONLY referenced from device code) ----------------
__device__ __align__(16) float g_xw[NN * DD];   // X@W (layer1 raw; layer2 pre-scaled by dinv)
__device__ __align__(16) float g_h[NN * DD];    // layer1 output (post BN+ReLU)
__device__ float g_dinv[NN];
__device__ int   g_degi[NN];
__device__ int   g_doff[NN + 1];
__device__ int   g_dcur[NN];
__device__ int   g_src32[EE];
__device__ int   g_dst32[EE];
__device__ int   g_ssorted[EE];
__device__ int   g_egr[EE];
__device__ int   g_eperm[EE];
__device__ int   g_nb32[NN];
__device__ int   g_ecnt[GG];
__device__ int   g_gcnt[GG];
__device__ int   g_eoff[GG + 1];
__device__ int   g_ecur[GG];
__device__ __align__(16) float g_gsum[GG * DD];
__device__ __align__(16) float g_esum[GG * DD];
__device__ int   g_is64;

__device__ __forceinline__ void red_add_v4(float* addr, float4 v) {
    asm volatile("red.global.add.v4.f32 [%0], {%1, %2, %3, %4};"
                 :: "l"(__cvta_generic_to_global(addr)),
                    "f"(v.x), "f"(v.y), "f"(v.z), "f"(v.w)
                 : "memory");
}
__device__ __forceinline__ int clampi(int v, int lo, int hi) {
    return min(max(v, lo), hi);
}

// ---------------- init + dtype probe (merged; probe in block 0) ----------------
__global__ void k_init(const int* __restrict__ ei_raw) {
    if (blockIdx.x == 0) {
        __shared__ int nz;
        if (threadIdx.x == 0) nz = 0;
        __syncthreads();
        for (int i = threadIdx.x; i < 1024; i += blockDim.x)
            if (ei_raw[2 * i + 1] != 0) nz = 1;   // int64 iff all odd 32-bit words zero
        __syncthreads();
        if (threadIdx.x == 0) g_is64 = (nz == 0) ? 1 : 0;
    }
    int i = blockIdx.x * blockDim.x + threadIdx.x;
    int stride = gridDim.x * blockDim.x;
    for (int idx = i; idx < NN; idx += stride) {
        g_degi[idx] = 0;
        if (idx < GG * DD) { g_gsum[idx] = 0.f; g_esum[idx] = 0.f; }
        if (idx < GG) { g_ecnt[idx] = 0; g_gcnt[idx] = 0; }
    }
}

// ---------------- edge prep ----------------
__global__ void k_edge_prep(const void* __restrict__ ei_raw,
                            const void* __restrict__ batch_raw) {
    __shared__ int hist[GG];
    for (int t = threadIdx.x; t < GG; t += blockDim.x) hist[t] = 0;
    __syncthreads();
    const int is64 = g_is64;
    const int*       ei32 = (const int*)ei_raw;
    const long long* ei64 = (const long long*)ei_raw;
    const int*       bt32 = (const int*)batch_raw;
    const long long* bt64 = (const long long*)batch_raw;
    int i0 = blockIdx.x * blockDim.x + threadIdx.x;
    int stride = gridDim.x * blockDim.x;
    for (int e = i0; e < EE; e += stride) {
        int s, d;
        if (is64) { s = (int)ei64[e]; d = (int)ei64[EE + e]; }
        else      { s = ei32[e];      d = ei32[EE + e]; }
        s = clampi(s, 0, NN - 1);
        d = clampi(d, 0, NN - 1);
        g_src32[e] = s;
        g_dst32[e] = d;
        atomicAdd(&g_degi[d], 1);
        int gr = is64 ? (int)bt64[s] : bt32[s];
        gr = clampi(gr, 0, GG - 1);
        g_egr[e] = gr;
        atomicAdd(&hist[gr], 1);
    }
    __syncthreads();
    for (int t = threadIdx.x; t < GG; t += blockDim.x)
        if (hist[t]) atomicAdd(&g_ecnt[t], hist[t]);
}

// ---------------- node prep ----------------
__global__ void k_node_prep(const void* __restrict__ batch_raw) {
    __shared__ int hist[GG];
    for (int t = threadIdx.x; t < GG; t += blockDim.x) hist[t] = 0;
    __syncthreads();
    const int is64 = g_is64;
    const int*       bt32 = (const int*)batch_raw;
    const long long* bt64 = (const long long*)batch_raw;
    int i0 = blockIdx.x * blockDim.x + threadIdx.x;
    int stride = gridDim.x * blockDim.x;
    for (int v = i0; v < NN; v += stride) {
        int gr = is64 ? (int)bt64[v] : bt32[v];
        gr = clampi(gr, 0, GG - 1);
        g_nb32[v] = gr;
        atomicAdd(&hist[gr], 1);
    }
    __syncthreads();
    for (int t = threadIdx.x; t < GG; t += blockDim.x)
        if (hist[t]) atomicAdd(&g_gcnt[t], hist[t]);
}

// ---------------- per-graph edge scan ----------------
__global__ void k_scan_graph() {
    __shared__ int s[GG];
    int t = threadIdx.x;
    int v = g_ecnt[t];
    s[t] = v;
    __syncthreads();
    for (int off = 1; off < GG; off <<= 1) {
        int add = (t >= off) ? s[t - off] : 0;
        __syncthreads();
        s[t] += add;
        __syncthreads();
    }
    int excl = s[t] - v;
    g_eoff[t] = excl;
    g_ecur[t] = excl;
    if (t == GG - 1) g_eoff[GG] = s[t];
}

// ---------------- CSR-by-dst scan + dinv ----------------
#define SCH 98
__global__ void k_scan_nodes() {
    __shared__ int part[1024];
    int t = threadIdx.x;
    int base = t * SCH;
    int sum = 0;
    for (int i = 0; i < SCH; i++) {
        int idx = base + i;
        if (idx < NN) sum += g_degi[idx];
    }
    part[t] = sum;
    __syncthreads();
    for (int off = 1; off < 1024; off <<= 1) {
        int add = (t >= off) ? part[t - off] : 0;
        __syncthreads();
        part[t] += add;
        __syncthreads();
    }
    int run = part[t] - sum;
    for (int i = 0; i < SCH; i++) {
        int idx = base + i;
        if (idx < NN) {
            g_doff[idx] = run;
            g_dcur[idx] = run;
            int dg = g_degi[idx];
            g_dinv[idx] = rsqrtf((float)(dg + 1));
            run += dg;
        }
    }
    if (t == 1023) g_doff[NN] = EE;
}

// ---------------- scatters (two separate passes; R12 proven) ----------------
__global__ void k_escatter_dst() {
    int i0 = blockIdx.x * blockDim.x + threadIdx.x;
    int stride = gridDim.x * blockDim.x;
    for (int e = i0; e < EE; e += stride) {
        int d = g_dst32[e];
        int q = atomicAdd(&g_dcur[d], 1);
        if (q < EE) g_ssorted[q] = g_src32[e];
    }
}
__global__ void k_escatter_graph() {
    int i0 = blockIdx.x * blockDim.x + threadIdx.x;
    int stride = gridDim.x * blockDim.x;
    for (int e = i0; e < EE; e += stride) {
        int gr = g_egr[e];
        int p = atomicAdd(&g_ecur[gr], 1);
        if (p < EE) g_eperm[p] = e;
    }
}

// ---------------- FFMA GEMM (proven), device-symbol-safe I/O ----------------
// LAYER 1: g_xw = Xarg @ W (raw).  LAYER 2: g_xw = (g_h @ W) * dinv[row].
template <int LAYER>
__global__ void __launch_bounds__(256) k_gemm_scale(const float* __restrict__ Xarg,
                                                    const float* __restrict__ W) {
    const float* __restrict__ Xp = (LAYER == 2) ? (const float*)g_h : Xarg;
    float* __restrict__ Out = g_xw;
    __shared__ __align__(16) float Xs[64 * 16];
    __shared__ __align__(16) float Ws[16 * 128];
    int tid = threadIdx.x;
    int tx = tid & 31, ty = tid >> 5;
    int r0 = blockIdx.x * 64;
    float acc[8][4];
#pragma unroll
    for (int i = 0; i < 8; i++)
#pragma unroll
        for (int j = 0; j < 4; j++) acc[i][j] = 0.f;

    for (int k0 = 0; k0 < 128; k0 += 16) {
        {
            int i0 = tid * 4;
            int row = i0 >> 4, kk = i0 & 15;
            int gr = r0 + row;
            float4 v = make_float4(0.f, 0.f, 0.f, 0.f);
            if (gr < NN) v = *(const float4*)&Xp[gr * 128 + k0 + kk];
            *(float4*)&Xs[row * 16 + kk] = v;
        }
        {
            int i0 = tid * 8;
            int r = i0 >> 7, c = i0 & 127;
            *(float4*)&Ws[r * 128 + c]     = *(const float4*)&W[(k0 + r) * 128 + c];
            *(float4*)&Ws[r * 128 + c + 4] = *(const float4*)&W[(k0 + r) * 128 + c + 4];
        }
        __syncthreads();
#pragma unroll
        for (int kk = 0; kk < 16; kk++) {
            float4 b = *(float4*)&Ws[kk * 128 + 4 * tx];
#pragma unroll
            for (int i = 0; i < 8; i++) {
                float a = Xs[(8 * ty + i) * 16 + kk];
                acc[i][0] = fmaf(a, b.x, acc[i][0]);
                acc[i][1] = fmaf(a, b.y, acc[i][1]);
                acc[i][2] = fmaf(a, b.z, acc[i][2]);
                acc[i][3] = fmaf(a, b.w, acc[i][3]);
            }
        }
        __syncthreads();
    }
#pragma unroll
    for (int i = 0; i < 8; i++) {
        int row = r0 + 8 * ty + i;
        if (row < NN) {
            float s = (LAYER == 2) ? g_dinv[row] : 1.0f;
            float4 o = make_float4(acc[i][0] * s, acc[i][1] * s, acc[i][2] * s, acc[i][3] * s);
            *(float4*)&Out[row * 128 + 4 * tx] = o;
        }
    }
}

// ---------------- fused aggregation + BN + ReLU (+ pool for layer 2) ----------------
template <int LAYER>
__global__ void __launch_bounds__(256) k_agg_fused(const float* __restrict__ b,
                                                   const float* __restrict__ gam,
                                                   const float* __restrict__ bet,
                                                   const float* __restrict__ mu,
                                                   const float* __restrict__ var) {
    int warp = (blockIdx.x * blockDim.x + threadIdx.x) >> 5;
    int lane = threadIdx.x & 31;
    if (warp >= NN) return;
    int v = warp;
    int dd = lane * 4;
    int lo = g_doff[v], hi = g_doff[v + 1];
    float dinv_v = g_dinv[v];

    float4 a0 = *(const float4*)&g_xw[v * 128 + dd];
    if (LAYER == 1) { a0.x *= dinv_v; a0.y *= dinv_v; a0.z *= dinv_v; a0.w *= dinv_v; }
    float4 a1 = make_float4(0.f, 0.f, 0.f, 0.f);
    float4 a2 = make_float4(0.f, 0.f, 0.f, 0.f);
    float4 a3 = make_float4(0.f, 0.f, 0.f, 0.f);
    int e = lo;
    for (; e + 3 < hi; e += 4) {
        int s0 = __ldg(&g_ssorted[e]);
        int s1 = __ldg(&g_ssorted[e + 1]);
        int s2 = __ldg(&g_ssorted[e + 2]);
        int s3 = __ldg(&g_ssorted[e + 3]);
        float4 v0 = *(const float4*)&g_xw[s0 * 128 + dd];
        float4 v1 = *(const float4*)&g_xw[s1 * 128 + dd];
        float4 v2 = *(const float4*)&g_xw[s2 * 128 + dd];
        float4 v3 = *(const float4*)&g_xw[s3 * 128 + dd];
        if (LAYER == 1) {
            float d0 = __ldg(&g_dinv[s0]);
            float d1 = __ldg(&g_dinv[s1]);
            float d2 = __ldg(&g_dinv[s2]);
            float d3 = __ldg(&g_dinv[s3]);
            a0.x = fmaf(v0.x, d0, a0.x); a0.y = fmaf(v0.y, d0, a0.y);
            a0.z = fmaf(v0.z, d0, a0.z); a0.w = fmaf(v0.w, d0, a0.w);
            a1.x = fmaf(v1.x, d1, a1.x); a1.y = fmaf(v1.y, d1, a1.y);
            a1.z = fmaf(v1.z, d1, a1.z); a1.w = fmaf(v1.w, d1, a1.w);
            a2.x = fmaf(v2.x, d2, a2.x); a2.y = fmaf(v2.y, d2, a2.y);
            a2.z = fmaf(v2.z, d2, a2.z); a2.w = fmaf(v2.w, d2, a2.w);
            a3.x = fmaf(v3.x, d3, a3.x); a3.y = fmaf(v3.y, d3, a3.y);
            a3.z = fmaf(v3.z, d3, a3.z); a3.w = fmaf(v3.w, d3, a3.w);
        } else {
            a0.x += v0.x; a0.y += v0.y; a0.z += v0.z; a0.w += v0.w;
            a1.x += v1.x; a1.y += v1.y; a1.z += v1.z; a1.w += v1.w;
            a2.x += v2.x; a2.y += v2.y; a2.z += v2.z; a2.w += v2.w;
            a3.x += v3.x; a3.y += v3.y; a3.z += v3.z; a3.w += v3.w;
        }
    }
    for (; e < hi; e++) {
        int s0 = __ldg(&g_ssorted[e]);
        float4 v0 = *(const float4*)&g_xw[s0 * 128 + dd];
        float d0 = (LAYER == 1) ? __ldg(&g_dinv[s0]) : 1.f;
        a0.x = fmaf(v0.x, d0, a0.x); a0.y = fmaf(v0.y, d0, a0.y);
        a0.z = fmaf(v0.z, d0, a0.z); a0.w = fmaf(v0.w, d0, a0.w);
    }
    float4 acc = make_float4(a0.x + a1.x + a2.x + a3.x,
                             a0.y + a1.y + a2.y + a3.y,
                             a0.z + a1.z + a2.z + a3.z,
                             a0.w + a1.w + a2.w + a3.w);

    float4 b4  = *(const float4*)&b[dd];
    float4 g4  = *(const float4*)&gam[dd];
    float4 t4  = *(const float4*)&bet[dd];
    float4 m4  = *(const float4*)&mu[dd];
    float4 v4  = *(const float4*)&var[dd];
    float s0c = g4.x * rsqrtf(v4.x + BN_EPS);
    float s1c = g4.y * rsqrtf(v4.y + BN_EPS);
    float s2c = g4.z * rsqrtf(v4.z + BN_EPS);
    float s3c = g4.w * rsqrtf(v4.w + BN_EPS);
    float c0 = (b4.x - m4.x) * s0c + t4.x;
    float c1 = (b4.y - m4.y) * s1c + t4.y;
    float c2 = (b4.z - m4.z) * s2c + t4.z;
    float c3 = (b4.w - m4.w) * s3c + t4.w;

    float4 r;
    r.x = fmaxf(dinv_v * acc.x * s0c + c0, 0.f);
    r.y = fmaxf(dinv_v * acc.y * s1c + c1, 0.f);
    r.z = fmaxf(dinv_v * acc.z * s2c + c2, 0.f);
    r.w = fmaxf(dinv_v * acc.w * s3c + c3, 0.f);

    if (LAYER == 1) {
        *(float4*)&g_h[v * 128 + dd] = r;
    } else {
        int gr = g_nb32[v];
        red_add_v4(&g_gsum[gr * 128 + dd], r);
    }
}

// ---------------- edge encoder (FFMA, best-measured) ----------------
#define ECHUNKS 3
__global__ void __launch_bounds__(128) k_edge_enc(const float* __restrict__ EA,
                                                  const float* __restrict__ We1,
                                                  const float* __restrict__ be1) {
    int g = blockIdx.x;
    int lo = g_eoff[g], hi = g_eoff[g + 1];
    int cnt = hi - lo;
    int y = blockIdx.y;
    int cl = lo + (int)((long long)cnt * y / ECHUNKS);
    int ch = lo + (int)((long long)cnt * (y + 1) / ECHUNKS);
    int lane = threadIdx.x & 31;
    int w = threadIdx.x >> 5;

    float wr0[16], wr1[16], wr2[16], wr3[16];
#pragma unroll
    for (int k = 0; k < 16; k++) {
        wr0[k] = __ldg(&We1[k * 128 + lane]);
        wr1[k] = __ldg(&We1[k * 128 + 32 + lane]);
        wr2[k] = __ldg(&We1[k * 128 + 64 + lane]);
        wr3[k] = __ldg(&We1[k * 128 + 96 + lane]);
    }
    float br0 = __ldg(&be1[lane]);
    float br1 = __ldg(&be1[32 + lane]);
    float br2 = __ldg(&be1[64 + lane]);
    float br3 = __ldg(&be1[96 + lane]);
    float a0 = 0.f, a1 = 0.f, a2 = 0.f, a3 = 0.f;

    __shared__ __align__(16) float4 s_ea[128 * 4];
    for (int base = cl; base < ch; base += 128) {
        int n = min(128, ch - base);
        if ((int)threadIdx.x < n) {
            int e = g_eperm[base + threadIdx.x];
            const float4* p = (const float4*)&EA[(long long)e * 16];
            s_ea[threadIdx.x * 4 + 0] = __ldg(&p[0]);
            s_ea[threadIdx.x * 4 + 1] = __ldg(&p[1]);
            s_ea[threadIdx.x * 4 + 2] = __ldg(&p[2]);
            s_ea[threadIdx.x * 4 + 3] = __ldg(&p[3]);
        }
        __syncthreads();
        for (int j = w; j < n; j += 4) {
            float o0 = br0, o1 = br1, o2 = br2, o3 = br3;
#pragma unroll
            for (int q = 0; q < 4; q++) {
                float4 A = s_ea[j * 4 + q];
                float av[4] = {A.x, A.y, A.z, A.w};
#pragma unroll
                for (int kk = 0; kk < 4; kk++) {
                    int k = q * 4 + kk;
                    float aa = av[kk];
                    o0 = fmaf(aa, wr0[k], o0);
                    o1 = fmaf(aa, wr1[k], o1);
                    o2 = fmaf(aa, wr2[k], o2);
                    o3 = fmaf(aa, wr3[k], o3);
                }
            }
            a0 += fmaxf(o0, 0.f);
            a1 += fmaxf(o1, 0.f);
            a2 += fmaxf(o2, 0.f);
            a3 += fmaxf(o3, 0.f);
        }
        __syncthreads();
    }
    __shared__ float s_red[4][128];
    s_red[w][lane] = a0;
    s_red[w][32 + lane] = a1;
    s_red[w][64 + lane] = a2;
    s_red[w][96 + lane] = a3;
    __syncthreads();
    int t = threadIdx.x;
    float tot = s_red[0][t] + s_red[1][t] + s_red[2][t] + s_red[3][t];
    atomicAdd(&g_esum[g * 128 + t], tot);
}

// ---------------- final ----------------
__global__ void k_final(const float* __restrict__ We2, const float* __restrict__ be2,
                        float* __restrict__ out) {
    int g = blockIdx.x;
    int t = threadIdx.x;
    __shared__ float mh[128];
    int ec = g_ecnt[g];
    float inv = 1.0f / (float)max(ec, 1);
    mh[t] = g_esum[g * 128 + t] * inv;
    __syncthreads();
    float er = 0.f;
    if (ec > 0) {
#pragma unroll 8
        for (int k = 0; k < 128; k++)
            er = fmaf(mh[k], __ldg(&We2[k * 128 + t]), er);
        er += __ldg(&be2[t]);
    }
    float nc = (float)g_gcnt[g];
    float grp = g_gsum[g * 128 + t] / fmaxf(nc, 1.0f);
    out[g * 128 + t] = grp + er;
}

// ---------------- launch (R12 structure) ----------------
extern "C" void kernel_launch(void* const* d_in, const int* in_sizes, int n_in,
                              void* d_out, int out_size) {
    const float* x     = (const float*)d_in[0];
    const void*  ei    = d_in[1];
    const void*  batch = d_in[2];
    const float* ea    = (const float*)d_in[3];
    int base = n_in - 16;
    const float* W1  = (const float*)d_in[base + 0];
    const float* b1  = (const float*)d_in[base + 1];
    const float* g1  = (const float*)d_in[base + 2];
    const float* bt1 = (const float*)d_in[base + 3];
    const float* m1  = (const float*)d_in[base + 4];
    const float* v1  = (const float*)d_in[base + 5];
    const float* W2  = (const float*)d_in[base + 6];
    const float* b2  = (const float*)d_in[base + 7];
    const float* g2  = (const float*)d_in[base + 8];
    const float* bt2 = (const float*)d_in[base + 9];
    const float* m2  = (const float*)d_in[base + 10];
    const float* v2  = (const float*)d_in[base + 11];
    const float* We1 = (const float*)d_in[base + 12];
    const float* be1 = (const float*)d_in[base + 13];
    const float* We2 = (const float*)d_in[base + 14];
    const float* be2 = (const float*)d_in[base + 15];
    float* out = (float*)d_out;

    static cudaStream_t sEnc = 0, sGemm = 0;
    static cudaEvent_t evRoot = 0, evPrep = 0, evGemm1 = 0, evEnc = 0;
    if (sEnc == 0) {
        cudaStreamCreateWithFlags(&sEnc, cudaStreamNonBlocking);
        cudaStreamCreateWithFlags(&sGemm, cudaStreamNonBlocking);
        cudaEventCreateWithFlags(&evRoot,  cudaEventDisableTiming);
        cudaEventCreateWithFlags(&evPrep,  cudaEventDisableTiming);
        cudaEventCreateWithFlags(&evGemm1, cudaEventDisableTiming);
        cudaEventCreateWithFlags(&evEnc,   cudaEventDisableTiming);
    }

    const int GEMM_BLOCKS = (NN + 63) / 64;

    // first op on origin stream (init includes dtype probe); then fork side streams
    k_init<<<512, 256>>>((const int*)ei);
    cudaEventRecord(evRoot, 0);

    // gemm1 (raw X@W1, no dinv dep) overlaps the prep chain
    cudaStreamWaitEvent(sGemm, evRoot, 0);
    k_gemm_scale<1><<<GEMM_BLOCKS, 256, 0, sGemm>>>(x, W1);
    cudaEventRecord(evGemm1, sGemm);

    k_edge_prep<<<2048, 256>>>(ei, batch);

    cudaEventRecord(evPrep, 0);
    cudaStreamWaitEvent(sEnc, evPrep, 0);
    k_scan_graph<<<1, GG, 0, sEnc>>>();
    k_escatter_graph<<<2048, 256, 0, sEnc>>>();
    {
        dim3 grid(GG, ECHUNKS);
        k_edge_enc<<<grid, 128, 0, sEnc>>>(ea, We1, be1);
    }
    cudaEventRecord(evEnc, sEnc);

    k_node_prep<<<512, 256>>>(batch);
    k_scan_nodes<<<1, 1024>>>();
    k_escatter_dst<<<2048, 256>>>();

    const int AGG_BLOCKS = (NN * 32 + 255) / 256;
    cudaStreamWaitEvent(0, evGemm1, 0);
    k_agg_fused<1><<<AGG_BLOCKS, 256>>>(b1, g1, bt1, m1, v1);

    k_gemm_scale<2><<<GEMM_BLOCKS, 256>>>(nullptr, W2);
    cudaStreamWaitEvent(0, evEnc, 0);
    k_agg_fused<2><<<AGG_BLOCKS, 256>>>(b2, g2, bt2, m2, v2);

    k_final<<<GG, 128>>>(We2, be2, out);
}